// round 1
// baseline (speedup 1.0000x reference)
#include <cuda_runtime.h>
#include <cuda_bf16.h>

#define BB 2
#define SS 2048
#define DD 1024
#define HH 16
#define HD 64
#define MM 4096
#define LOG2E 1.4426950408889634f

__device__ float g_q[MM * DD];
__device__ float g_k[MM * DD];
__device__ float g_v[MM * DD];
__device__ float g_attn[MM * DD];
__device__ float g_mask[BB * SS];
__device__ int   g_maskflag;

__global__ void detect_mask_kernel(const unsigned char* __restrict__ p) {
    __shared__ int f1, f23, f4;
    int tid = threadIdx.x;
    if (tid == 0) { f1 = 0; f23 = 0; f4 = 0; }
    __syncthreads();
    int l1 = 0, l23 = 0, l4 = 0;
    for (int i = tid; i < BB * SS; i += blockDim.x) {
        unsigned char v = p[i];
        if (v) {
            int r = i & 3;
            if (r == 1) l1 = 1;
            else if (r == 2 || r == 3) l23 = 1;
            if ((i & 7) == 4) l4 = 1;
        }
    }
    if (l1)  atomicOr(&f1, 1);
    if (l23) atomicOr(&f23, 1);
    if (l4)  atomicOr(&f4, 1);
    __syncthreads();
    if (tid == 0) {
        int flag;
        if (f1) flag = 0;
        else if (f23) flag = 2;
        else if (f4) flag = 1;
        else flag = 3;
        g_maskflag = flag;
    }
}

__global__ void repack_mask_kernel(const void* __restrict__ p) {
    int i = blockIdx.x * blockDim.x + threadIdx.x;
    if (i >= BB * SS) return;
    int flag = g_maskflag;
    bool mv;
    if (flag == 0)      mv = ((const unsigned char*)p)[i] != 0;
    else if (flag == 1) mv = ((const int*)p)[i] != 0;
    else if (flag == 2) mv = ((const float*)p)[i] != 0.0f;
    else                mv = ((const long long*)p)[i] != 0;
    g_mask[i] = mv ? -1.0e9f : 0.0f;
}

// SGEMM NT: C[m,n] = sum_k A[m,k]*W[n,k] + bias[n]
// srcsel: 0 -> A param, 1 -> g_attn
// dstsel: 0 -> C param plain [M,N]; 1/2/3 -> g_q/g_k/g_v permuted to [B,H,S,HD]
__global__ __launch_bounds__(256, 2)
void gemm_nt_bias(const float* __restrict__ A, const float* __restrict__ W,
                  const float* __restrict__ bias, float* __restrict__ C,
                  int srcsel, int dstsel)
{
    __shared__ float As[16][128];
    __shared__ float Bs[16][128];
    const int K = DD, N = DD;

    const float* Abase = (srcsel == 0) ? A : g_attn;
    float* Cbase = (dstsel == 0) ? C : (dstsel == 1 ? g_q : (dstsel == 2 ? g_k : g_v));

    int tid  = threadIdx.x;
    int trow = tid >> 4;
    int tcol = tid & 15;
    int lr = tid >> 2;
    int lk = (tid & 3) << 2;

    const float* Ap = Abase + ((size_t)((blockIdx.y << 7) + lr)) * K + lk;
    const float* Wp = W + ((size_t)((blockIdx.x << 7) + lr)) * K + lk;

    float acc[8][8];
#pragma unroll
    for (int i = 0; i < 8; i++)
#pragma unroll
        for (int j = 0; j < 8; j++) acc[i][j] = 0.0f;

    for (int kt = 0; kt < K; kt += 16) {
        float4 a0 = *(const float4*)(Ap + kt);
        float4 a1 = *(const float4*)(Ap + (size_t)64 * K + kt);
        float4 b0 = *(const float4*)(Wp + kt);
        float4 b1 = *(const float4*)(Wp + (size_t)64 * K + kt);
        __syncthreads();
        As[lk + 0][lr] = a0.x; As[lk + 1][lr] = a0.y;
        As[lk + 2][lr] = a0.z; As[lk + 3][lr] = a0.w;
        As[lk + 0][lr + 64] = a1.x; As[lk + 1][lr + 64] = a1.y;
        As[lk + 2][lr + 64] = a1.z; As[lk + 3][lr + 64] = a1.w;
        Bs[lk + 0][lr] = b0.x; Bs[lk + 1][lr] = b0.y;
        Bs[lk + 2][lr] = b0.z; Bs[lk + 3][lr] = b0.w;
        Bs[lk + 0][lr + 64] = b1.x; Bs[lk + 1][lr + 64] = b1.y;
        Bs[lk + 2][lr + 64] = b1.z; Bs[lk + 3][lr + 64] = b1.w;
        __syncthreads();
#pragma unroll
        for (int kk = 0; kk < 16; kk++) {
            float a[8], b[8];
            *(float4*)(a)     = *(const float4*)&As[kk][trow << 2];
            *(float4*)(a + 4) = *(const float4*)&As[kk][(trow << 2) + 64];
            *(float4*)(b)     = *(const float4*)&Bs[kk][tcol << 2];
            *(float4*)(b + 4) = *(const float4*)&Bs[kk][(tcol << 2) + 64];
#pragma unroll
            for (int i = 0; i < 8; i++)
#pragma unroll
                for (int j = 0; j < 8; j++)
                    acc[i][j] += a[i] * b[j];
        }
    }

#pragma unroll
    for (int ri = 0; ri < 2; ri++) {
#pragma unroll
        for (int i = 0; i < 4; i++) {
            int m = (blockIdx.y << 7) + (trow << 2) + ri * 64 + i;
#pragma unroll
            for (int ci = 0; ci < 2; ci++) {
                int n = (blockIdx.x << 7) + (tcol << 2) + ci * 64;
                float4 v;
                v.x = acc[ri * 4 + i][ci * 4 + 0] + bias[n + 0];
                v.y = acc[ri * 4 + i][ci * 4 + 1] + bias[n + 1];
                v.z = acc[ri * 4 + i][ci * 4 + 2] + bias[n + 2];
                v.w = acc[ri * 4 + i][ci * 4 + 3] + bias[n + 3];
                if (dstsel == 0) {
                    *(float4*)&Cbase[(size_t)m * N + n] = v;
                } else {
                    int bb = m >> 11, s = m & 2047, h = n >> 6, hd = n & 63;
                    *(float4*)&Cbase[((((size_t)bb << 4) + h) * SS + s) * HD + hd] = v;
                }
            }
        }
    }
}

__device__ __forceinline__ int swz(int d, int i) {
    return d * 64 + ((((i >> 2) ^ (d & 15)) << 2) | (i & 3));
}

__global__ __launch_bounds__(256, 2)
void flash_attn_fp32()
{
    __shared__ float sQ[4096];
    __shared__ float sKP[4096];
    __shared__ float sV[4096];

    int tid = threadIdx.x;
    int ty = tid >> 4, tx = tid & 15;
    int bh = blockIdx.y;
    int b = bh >> 4, h = bh & 15;
    int qt = (int)gridDim.x - 1 - (int)blockIdx.x;
    int q0 = qt << 6;

    const float* Qp = g_q + ((size_t)bh * SS + q0) * HD;
    const float* Kp = g_k + (size_t)bh * SS * HD;
    const float* Vp = g_v + (size_t)bh * SS * HD;

    {
        int i0 = tid >> 4;
        int d0 = (tid & 15) << 2;
#pragma unroll
        for (int p = 0; p < 4; p++) {
            int row = i0 + (p << 4);
            float4 v = *(const float4*)(Qp + row * HD + d0);
            sQ[swz(d0 + 0, row)] = v.x;
            sQ[swz(d0 + 1, row)] = v.y;
            sQ[swz(d0 + 2, row)] = v.z;
            sQ[swz(d0 + 3, row)] = v.w;
        }
    }

    float m_i[4], l_i[4], o[4][4];
#pragma unroll
    for (int i = 0; i < 4; i++) {
        m_i[i] = -1e30f; l_i[i] = 0.0f;
#pragma unroll
        for (int j = 0; j < 4; j++) o[i][j] = 0.0f;
    }

    for (int jt = 0; jt <= qt; jt++) {
        int j0 = jt << 6;
        __syncthreads();
        {
            int i0 = tid >> 4;
            int d0 = (tid & 15) << 2;
            const float* kp = Kp + (size_t)j0 * HD;
            const float* vp = Vp + (size_t)j0 * HD;
#pragma unroll
            for (int p = 0; p < 4; p++) {
                int row = i0 + (p << 4);
                float4 kv = *(const float4*)(kp + row * HD + d0);
                sKP[swz(d0 + 0, row)] = kv.x;
                sKP[swz(d0 + 1, row)] = kv.y;
                sKP[swz(d0 + 2, row)] = kv.z;
                sKP[swz(d0 + 3, row)] = kv.w;
                float4 vv = *(const float4*)(vp + row * HD + d0);
                *(float4*)&sV[row * HD + d0] = vv;
            }
        }
        float madd[4];
#pragma unroll
        for (int jj = 0; jj < 4; jj++)
            madd[jj] = g_mask[b * SS + j0 + (tx << 2) + jj];
        __syncthreads();

        float s[4][4];
#pragma unroll
        for (int ii = 0; ii < 4; ii++)
#pragma unroll
            for (int jj = 0; jj < 4; jj++) s[ii][jj] = 0.0f;
#pragma unroll 16
        for (int d = 0; d < 64; d++) {
            float qv[4], kv[4];
            *(float4*)qv = *(const float4*)&sQ[d * 64 + ((ty ^ (d & 15)) << 2)];
            *(float4*)kv = *(const float4*)&sKP[d * 64 + ((tx ^ (d & 15)) << 2)];
#pragma unroll
            for (int ii = 0; ii < 4; ii++)
#pragma unroll
                for (int jj = 0; jj < 4; jj++)
                    s[ii][jj] += qv[ii] * kv[jj];
        }

        bool diag = (jt == qt);
#pragma unroll
        for (int ii = 0; ii < 4; ii++)
#pragma unroll
            for (int jj = 0; jj < 4; jj++) {
                float sv = s[ii][jj] * 0.125f + madd[jj];
                if (diag && ((tx << 2) + jj > (ty << 2) + ii)) sv = -1.0e9f;
                s[ii][jj] = sv;
            }

#pragma unroll
        for (int ii = 0; ii < 4; ii++) {
            float rm = fmaxf(fmaxf(s[ii][0], s[ii][1]), fmaxf(s[ii][2], s[ii][3]));
#pragma unroll
            for (int off = 8; off > 0; off >>= 1)
                rm = fmaxf(rm, __shfl_xor_sync(0xffffffffu, rm, off, 16));
            float mnew = fmaxf(m_i[ii], rm);
            float corr = exp2f((m_i[ii] - mnew) * LOG2E);
            m_i[ii] = mnew;
            float rs = 0.0f;
#pragma unroll
            for (int jj = 0; jj < 4; jj++) {
                float pv = exp2f((s[ii][jj] - mnew) * LOG2E);
                s[ii][jj] = pv;
                rs += pv;
            }
#pragma unroll
            for (int off = 8; off > 0; off >>= 1)
                rs += __shfl_xor_sync(0xffffffffu, rs, off, 16);
            l_i[ii] = l_i[ii] * corr + rs;
#pragma unroll
            for (int jj = 0; jj < 4; jj++) o[ii][jj] *= corr;
        }

        __syncthreads();
#pragma unroll
        for (int ii = 0; ii < 4; ii++)
            *(float4*)&sKP[((ty << 2) + ii) * 64 + (tx << 2)] =
                make_float4(s[ii][0], s[ii][1], s[ii][2], s[ii][3]);
        __syncthreads();

#pragma unroll
        for (int j4 = 0; j4 < 16; j4++) {
            float pv[4][4], vv[4][4];
#pragma unroll
            for (int ii = 0; ii < 4; ii++)
                *(float4*)pv[ii] = *(const float4*)&sKP[((ty << 2) + ii) * 64 + (j4 << 2)];
#pragma unroll
            for (int k = 0; k < 4; k++)
                *(float4*)vv[k] = *(const float4*)&sV[((j4 << 2) + k) * 64 + (tx << 2)];
#pragma unroll
            for (int k = 0; k < 4; k++)
#pragma unroll
                for (int ii = 0; ii < 4; ii++)
#pragma unroll
                    for (int jj = 0; jj < 4; jj++)
                        o[ii][jj] += pv[ii][k] * vv[k][jj];
        }
    }

#pragma unroll
    for (int ii = 0; ii < 4; ii++) {
        float inv = 1.0f / l_i[ii];
        int row = q0 + (ty << 2) + ii;
        float4 ov = make_float4(o[ii][0] * inv, o[ii][1] * inv,
                                o[ii][2] * inv, o[ii][3] * inv);
        *(float4*)&g_attn[(((size_t)b * SS + row) << 10) + (h << 6) + (tx << 2)] = ov;
    }
}

extern "C" void kernel_launch(void* const* d_in, const int* in_sizes, int n_in,
                              void* d_out, int out_size) {
    const float* x  = (const float*)d_in[0];
    const void*  pm = d_in[1];
    const float* Wq = (const float*)d_in[2];
    const float* bq = (const float*)d_in[3];
    const float* Wk = (const float*)d_in[4];
    const float* bk = (const float*)d_in[5];
    const float* Wv = (const float*)d_in[6];
    const float* bv = (const float*)d_in[7];
    const float* Wo = (const float*)d_in[8];
    const float* bo = (const float*)d_in[9];
    float* out = (float*)d_out;

    detect_mask_kernel<<<1, 256>>>((const unsigned char*)pm);
    repack_mask_kernel<<<16, 256>>>(pm);

    dim3 gg(DD / 128, MM / 128), bb(256);
    gemm_nt_bias<<<gg, bb>>>(x, Wq, bq, nullptr, 0, 1);
    gemm_nt_bias<<<gg, bb>>>(x, Wk, bk, nullptr, 0, 2);
    gemm_nt_bias<<<gg, bb>>>(x, Wv, bv, nullptr, 0, 3);

    flash_attn_fp32<<<dim3(SS / 64, BB * HH), 256>>>();

    gemm_nt_bias<<<gg, bb>>>(nullptr, Wo, bo, out, 1, 0);
}

// round 4
// speedup vs baseline: 1.2004x; 1.2004x over previous
#include <cuda_runtime.h>
#include <cstdint>

typedef unsigned int u32;

#define BB 2
#define SS 2048
#define DD 1024
#define HH 16
#define HD 64
#define MM 4096
#define LOG2E 1.4426950408889634f

__device__ float g_q[MM * DD];
__device__ float g_k[MM * DD];
__device__ float g_v[MM * DD];
__device__ float g_attn[MM * DD];
__device__ float g_mask[BB * SS];
__device__ int   g_maskflag;

// ---------------------------------------------------------------------------
// Mask detect / repack (unchanged, proven)
// ---------------------------------------------------------------------------
__global__ void detect_mask_kernel(const unsigned char* __restrict__ p) {
    __shared__ int f1, f23, f4;
    int tid = threadIdx.x;
    if (tid == 0) { f1 = 0; f23 = 0; f4 = 0; }
    __syncthreads();
    int l1 = 0, l23 = 0, l4 = 0;
    for (int i = tid; i < BB * SS; i += blockDim.x) {
        unsigned char v = p[i];
        if (v) {
            int r = i & 3;
            if (r == 1) l1 = 1;
            else if (r == 2 || r == 3) l23 = 1;
            if ((i & 7) == 4) l4 = 1;
        }
    }
    if (l1)  atomicOr(&f1, 1);
    if (l23) atomicOr(&f23, 1);
    if (l4)  atomicOr(&f4, 1);
    __syncthreads();
    if (tid == 0) {
        int flag;
        if (f1) flag = 0;
        else if (f23) flag = 2;
        else if (f4) flag = 1;
        else flag = 3;
        g_maskflag = flag;
    }
}

__global__ void repack_mask_kernel(const void* __restrict__ p) {
    int i = blockIdx.x * blockDim.x + threadIdx.x;
    if (i >= BB * SS) return;
    int flag = g_maskflag;
    bool mv;
    if (flag == 0)      mv = ((const unsigned char*)p)[i] != 0;
    else if (flag == 1) mv = ((const int*)p)[i] != 0;
    else if (flag == 2) mv = ((const float*)p)[i] != 0.0f;
    else                mv = ((const long long*)p)[i] != 0;
    g_mask[i] = mv ? -1.0e9f : 0.0f;
}

// ---------------------------------------------------------------------------
// tf32 helpers (plain sm_103-legal PTX: cvt + mma.sync, no tcgen05)
// ---------------------------------------------------------------------------
__device__ __forceinline__ u32 tf32rn(float x) {
    u32 r; asm("cvt.rna.tf32.f32 %0, %1;" : "=r"(r) : "f"(x)); return r;
}
__device__ __forceinline__ void mma8(float* c, const u32* a, const u32* b) {
    asm volatile("mma.sync.aligned.m16n8k8.row.col.f32.tf32.tf32.f32 "
        "{%0,%1,%2,%3}, {%4,%5,%6,%7}, {%8,%9}, {%0,%1,%2,%3};"
        : "+f"(c[0]), "+f"(c[1]), "+f"(c[2]), "+f"(c[3])
        : "r"(a[0]), "r"(a[1]), "r"(a[2]), "r"(a[3]), "r"(b[0]), "r"(b[1]));
}

// ---------------------------------------------------------------------------
// Split-TF32 GEMM (NT): C[m,n] = sum_k A[m,k]*W[n,k] + bias[n]
// x = x_hi + x_lo (each tf32); y = hi*hi + hi*lo + lo*hi  (~fp32 accuracy)
// CTA 128x128, BK=32, 256 thr (8 warps of 32x64). smem tile stride 36 floats
// -> conflict-free fragment LDS (bank = 4*gid + tig).
// srcsel: 0 -> A param, 1 -> g_attn
// dstsel: 0 -> C param [M,N]; 1/2/3 -> g_q/g_k/g_v permuted [B,H,S,HD]
// ---------------------------------------------------------------------------
#define BK 32
#define TSTR 36
#define TILE_F (128 * TSTR)             // 4608 floats per tile
#define SM_AH 0
#define SM_BH TILE_F
#define SM_AL (2 * TILE_F)
#define SM_BL (3 * TILE_F)
#define GSM_BYTES (4 * TILE_F * 4)      // 73728 bytes

__global__ __launch_bounds__(256, 1)
void gemm_mma(const float* __restrict__ Ain, const float* __restrict__ W,
              const float* __restrict__ bias, float* __restrict__ Cout,
              int srcsel, int dstsel)
{
    extern __shared__ float smf[];
    const float* A = srcsel ? g_attn : Ain;
    float* C = (dstsel == 0) ? Cout : (dstsel == 1 ? g_q : (dstsel == 2 ? g_k : g_v));

    int tid = threadIdx.x, wid = tid >> 5, lane = tid & 31;
    int gid = lane >> 2, tig = lane & 3;
    int m0 = (int)blockIdx.y << 7, n0 = (int)blockIdx.x << 7;
    int wm = (wid & 3) * 32, wn = (wid >> 2) * 64;

    const float* pA = A + (size_t)(m0 + (tid >> 3)) * DD + (tid & 7) * 4;
    const float* pB = W + (size_t)(n0 + (tid >> 3)) * DD + (tid & 7) * 4;
    int sbase = (tid >> 3) * TSTR + (tid & 7) * 4;

    float acc[2][8][4];
#pragma unroll
    for (int mt = 0; mt < 2; mt++)
#pragma unroll
        for (int nt = 0; nt < 8; nt++)
#pragma unroll
            for (int i = 0; i < 4; i++) acc[mt][nt][i] = 0.0f;

    float4 ra[4], rb[4];
#pragma unroll
    for (int j = 0; j < 4; j++) {
        ra[j] = *(const float4*)(pA + (size_t)j * 32 * DD);
        rb[j] = *(const float4*)(pB + (size_t)j * 32 * DD);
    }

    const int nk = DD / BK;
    for (int kt = 0; kt < nk; kt++) {
        __syncthreads();
        // STS: split into hi (tf32) + lo (residual, tf32)
#pragma unroll
        for (int j = 0; j < 4; j++) {
            int off = sbase + j * 32 * TSTR;
            u32 hx = tf32rn(ra[j].x), hy = tf32rn(ra[j].y);
            u32 hz = tf32rn(ra[j].z), hw = tf32rn(ra[j].w);
            float4 h = make_float4(__uint_as_float(hx), __uint_as_float(hy),
                                   __uint_as_float(hz), __uint_as_float(hw));
            *(float4*)&smf[SM_AH + off] = h;
            float4 l = make_float4(ra[j].x - h.x, ra[j].y - h.y,
                                   ra[j].z - h.z, ra[j].w - h.w);
            *(float4*)&smf[SM_AL + off] =
                make_float4(__uint_as_float(tf32rn(l.x)), __uint_as_float(tf32rn(l.y)),
                            __uint_as_float(tf32rn(l.z)), __uint_as_float(tf32rn(l.w)));
            hx = tf32rn(rb[j].x); hy = tf32rn(rb[j].y);
            hz = tf32rn(rb[j].z); hw = tf32rn(rb[j].w);
            h = make_float4(__uint_as_float(hx), __uint_as_float(hy),
                            __uint_as_float(hz), __uint_as_float(hw));
            *(float4*)&smf[SM_BH + off] = h;
            l = make_float4(rb[j].x - h.x, rb[j].y - h.y,
                            rb[j].z - h.z, rb[j].w - h.w);
            *(float4*)&smf[SM_BL + off] =
                make_float4(__uint_as_float(tf32rn(l.x)), __uint_as_float(tf32rn(l.y)),
                            __uint_as_float(tf32rn(l.z)), __uint_as_float(tf32rn(l.w)));
        }
        __syncthreads();
        if (kt + 1 < nk) {
#pragma unroll
            for (int j = 0; j < 4; j++) {
                ra[j] = *(const float4*)(pA + (size_t)j * 32 * DD + (kt + 1) * BK);
                rb[j] = *(const float4*)(pB + (size_t)j * 32 * DD + (kt + 1) * BK);
            }
        }
#pragma unroll
        for (int ks = 0; ks < 4; ks++) {
            int ko = ks * 8;
            u32 ah[2][4], al[2][4];
#pragma unroll
            for (int mt = 0; mt < 2; mt++) {
                int base = (wm + mt * 16 + gid) * TSTR + ko + tig;
                ah[mt][0] = __float_as_uint(smf[SM_AH + base]);
                ah[mt][1] = __float_as_uint(smf[SM_AH + base + 8 * TSTR]);
                ah[mt][2] = __float_as_uint(smf[SM_AH + base + 4]);
                ah[mt][3] = __float_as_uint(smf[SM_AH + base + 8 * TSTR + 4]);
                al[mt][0] = __float_as_uint(smf[SM_AL + base]);
                al[mt][1] = __float_as_uint(smf[SM_AL + base + 8 * TSTR]);
                al[mt][2] = __float_as_uint(smf[SM_AL + base + 4]);
                al[mt][3] = __float_as_uint(smf[SM_AL + base + 8 * TSTR + 4]);
            }
            u32 bh[8][2], bl[8][2];
#pragma unroll
            for (int nt = 0; nt < 8; nt++) {
                int base = (wn + nt * 8 + gid) * TSTR + ko + tig;
                bh[nt][0] = __float_as_uint(smf[SM_BH + base]);
                bh[nt][1] = __float_as_uint(smf[SM_BH + base + 4]);
                bl[nt][0] = __float_as_uint(smf[SM_BL + base]);
                bl[nt][1] = __float_as_uint(smf[SM_BL + base + 4]);
            }
#pragma unroll
            for (int mt = 0; mt < 2; mt++)
#pragma unroll
                for (int nt = 0; nt < 8; nt++) {
                    mma8(acc[mt][nt], ah[mt], bh[nt]);
                    mma8(acc[mt][nt], ah[mt], bl[nt]);
                    mma8(acc[mt][nt], al[mt], bh[nt]);
                }
        }
    }

    // Epilogue: C frag rows gid/gid+8, col pair 2*tig
#pragma unroll
    for (int mt = 0; mt < 2; mt++)
#pragma unroll
        for (int nt = 0; nt < 8; nt++) {
            int m = m0 + wm + mt * 16 + gid;
            int n = n0 + wn + nt * 8 + tig * 2;
            float b0 = bias[n], b1 = bias[n + 1];
            float2 p0 = make_float2(acc[mt][nt][0] + b0, acc[mt][nt][1] + b1);
            float2 p1 = make_float2(acc[mt][nt][2] + b0, acc[mt][nt][3] + b1);
            if (dstsel == 0) {
                *(float2*)&C[(size_t)m * DD + n] = p0;
                *(float2*)&C[(size_t)(m + 8) * DD + n] = p1;
            } else {
                int h = n >> 6, hd = n & 63;
                int b_ = m >> 11, s = m & 2047;
                *(float2*)&C[(((size_t)(b_ * 16 + h)) * SS + s) * HD + hd] = p0;
                int b2 = (m + 8) >> 11, s2 = (m + 8) & 2047;
                *(float2*)&C[(((size_t)(b2 * 16 + h)) * SS + s2) * HD + hd] = p1;
            }
        }
}

// ---------------------------------------------------------------------------
// Flash attention fp32 (unchanged from R1 — proven, rel_err 8.7e-7)
// ---------------------------------------------------------------------------
__device__ __forceinline__ int swzf(int d, int i) {
    return d * 64 + ((((i >> 2) ^ (d & 15)) << 2) | (i & 3));
}

__global__ __launch_bounds__(256, 2)
void flash_attn_fp32()
{
    __shared__ float sQ[4096];
    __shared__ float sKP[4096];
    __shared__ float sV[4096];

    int tid = threadIdx.x;
    int ty = tid >> 4, tx = tid & 15;
    int bh = blockIdx.y;
    int b = bh >> 4, h = bh & 15;
    int qt = (int)gridDim.x - 1 - (int)blockIdx.x;
    int q0 = qt << 6;

    const float* Qp = g_q + ((size_t)bh * SS + q0) * HD;
    const float* Kp = g_k + (size_t)bh * SS * HD;
    const float* Vp = g_v + (size_t)bh * SS * HD;

    {
        int i0 = tid >> 4;
        int d0 = (tid & 15) << 2;
#pragma unroll
        for (int p = 0; p < 4; p++) {
            int row = i0 + (p << 4);
            float4 v = *(const float4*)(Qp + row * HD + d0);
            sQ[swzf(d0 + 0, row)] = v.x;
            sQ[swzf(d0 + 1, row)] = v.y;
            sQ[swzf(d0 + 2, row)] = v.z;
            sQ[swzf(d0 + 3, row)] = v.w;
        }
    }

    float m_i[4], l_i[4], o[4][4];
#pragma unroll
    for (int i = 0; i < 4; i++) {
        m_i[i] = -1e30f; l_i[i] = 0.0f;
#pragma unroll
        for (int j = 0; j < 4; j++) o[i][j] = 0.0f;
    }

    for (int jt = 0; jt <= qt; jt++) {
        int j0 = jt << 6;
        __syncthreads();
        {
            int i0 = tid >> 4;
            int d0 = (tid & 15) << 2;
            const float* kp = Kp + (size_t)j0 * HD;
            const float* vp = Vp + (size_t)j0 * HD;
#pragma unroll
            for (int p = 0; p < 4; p++) {
                int row = i0 + (p << 4);
                float4 kv = *(const float4*)(kp + row * HD + d0);
                sKP[swzf(d0 + 0, row)] = kv.x;
                sKP[swzf(d0 + 1, row)] = kv.y;
                sKP[swzf(d0 + 2, row)] = kv.z;
                sKP[swzf(d0 + 3, row)] = kv.w;
                float4 vv = *(const float4*)(vp + row * HD + d0);
                *(float4*)&sV[row * HD + d0] = vv;
            }
        }
        float madd[4];
#pragma unroll
        for (int jj = 0; jj < 4; jj++)
            madd[jj] = g_mask[b * SS + j0 + (tx << 2) + jj];
        __syncthreads();

        float s[4][4];
#pragma unroll
        for (int ii = 0; ii < 4; ii++)
#pragma unroll
            for (int jj = 0; jj < 4; jj++) s[ii][jj] = 0.0f;
#pragma unroll 16
        for (int d = 0; d < 64; d++) {
            float qv[4], kv[4];
            *(float4*)qv = *(const float4*)&sQ[d * 64 + ((ty ^ (d & 15)) << 2)];
            *(float4*)kv = *(const float4*)&sKP[d * 64 + ((tx ^ (d & 15)) << 2)];
#pragma unroll
            for (int ii = 0; ii < 4; ii++)
#pragma unroll
                for (int jj = 0; jj < 4; jj++)
                    s[ii][jj] += qv[ii] * kv[jj];
        }

        bool diag = (jt == qt);
#pragma unroll
        for (int ii = 0; ii < 4; ii++)
#pragma unroll
            for (int jj = 0; jj < 4; jj++) {
                float sv = s[ii][jj] * 0.125f + madd[jj];
                if (diag && ((tx << 2) + jj > (ty << 2) + ii)) sv = -1.0e9f;
                s[ii][jj] = sv;
            }

#pragma unroll
        for (int ii = 0; ii < 4; ii++) {
            float rm = fmaxf(fmaxf(s[ii][0], s[ii][1]), fmaxf(s[ii][2], s[ii][3]));
#pragma unroll
            for (int off = 8; off > 0; off >>= 1)
                rm = fmaxf(rm, __shfl_xor_sync(0xffffffffu, rm, off, 16));
            float mnew = fmaxf(m_i[ii], rm);
            float corr = exp2f((m_i[ii] - mnew) * LOG2E);
            m_i[ii] = mnew;
            float rs = 0.0f;
#pragma unroll
            for (int jj = 0; jj < 4; jj++) {
                float pv = exp2f((s[ii][jj] - mnew) * LOG2E);
                s[ii][jj] = pv;
                rs += pv;
            }
#pragma unroll
            for (int off = 8; off > 0; off >>= 1)
                rs += __shfl_xor_sync(0xffffffffu, rs, off, 16);
            l_i[ii] = l_i[ii] * corr + rs;
#pragma unroll
            for (int jj = 0; jj < 4; jj++) o[ii][jj] *= corr;
        }

        __syncthreads();
#pragma unroll
        for (int ii = 0; ii < 4; ii++)
            *(float4*)&sKP[((ty << 2) + ii) * 64 + (tx << 2)] =
                make_float4(s[ii][0], s[ii][1], s[ii][2], s[ii][3]);
        __syncthreads();

#pragma unroll
        for (int j4 = 0; j4 < 16; j4++) {
            float pv[4][4], vv[4][4];
#pragma unroll
            for (int ii = 0; ii < 4; ii++)
                *(float4*)pv[ii] = *(const float4*)&sKP[((ty << 2) + ii) * 64 + (j4 << 2)];
#pragma unroll
            for (int k = 0; k < 4; k++)
                *(float4*)vv[k] = *(const float4*)&sV[((j4 << 2) + k) * 64 + (tx << 2)];
#pragma unroll
            for (int k = 0; k < 4; k++)
#pragma unroll
                for (int ii = 0; ii < 4; ii++)
#pragma unroll
                    for (int jj = 0; jj < 4; jj++)
                        o[ii][jj] += pv[ii][k] * vv[k][jj];
        }
    }

#pragma unroll
    for (int ii = 0; ii < 4; ii++) {
        float inv = 1.0f / l_i[ii];
        int row = q0 + (ty << 2) + ii;
        float4 ov = make_float4(o[ii][0] * inv, o[ii][1] * inv,
                                o[ii][2] * inv, o[ii][3] * inv);
        *(float4*)&g_attn[(((size_t)b * SS + row) << 10) + (h << 6) + (tx << 2)] = ov;
    }
}

// ---------------------------------------------------------------------------
extern "C" void kernel_launch(void* const* d_in, const int* in_sizes, int n_in,
                              void* d_out, int out_size) {
    const float* x  = (const float*)d_in[0];
    const void*  pm = d_in[1];
    const float* Wq = (const float*)d_in[2];
    const float* bq = (const float*)d_in[3];
    const float* Wk = (const float*)d_in[4];
    const float* bk = (const float*)d_in[5];
    const float* Wv = (const float*)d_in[6];
    const float* bv = (const float*)d_in[7];
    const float* Wo = (const float*)d_in[8];
    const float* bo = (const float*)d_in[9];
    float* out = (float*)d_out;

    cudaFuncSetAttribute(gemm_mma, cudaFuncAttributeMaxDynamicSharedMemorySize, GSM_BYTES);

    detect_mask_kernel<<<1, 256>>>((const unsigned char*)pm);
    repack_mask_kernel<<<16, 256>>>(pm);

    dim3 gg(DD / 128, MM / 128);   // (8, 32)
    gemm_mma<<<gg, 256, GSM_BYTES>>>(x, Wq, bq, nullptr, 0, 1);
    gemm_mma<<<gg, 256, GSM_BYTES>>>(x, Wk, bk, nullptr, 0, 2);
    gemm_mma<<<gg, 256, GSM_BYTES>>>(x, Wv, bv, nullptr, 0, 3);

    flash_attn_fp32<<<dim3(SS / 64, BB * HH), 256>>>();

    gemm_mma<<<gg, 256, GSM_BYTES>>>(nullptr, Wo, bo, out, 1, 0);
}

// round 6
// speedup vs baseline: 1.3394x; 1.1158x over previous
#include <cuda_runtime.h>
#include <cstdint>

typedef unsigned int u32;

#define BB 2
#define SS 2048
#define DD 1024
#define HH 16
#define HD 64
#define MM 4096
#define LOG2E 1.4426950408889634f

__device__ float g_q[MM * DD];
__device__ float g_k[MM * DD];
__device__ float g_v[MM * DD];
__device__ float g_attn[MM * DD];
__device__ float g_mask[BB * SS];
__device__ int   g_maskflag;

// ---------------------------------------------------------------------------
// Mask detect / repack (proven)
// ---------------------------------------------------------------------------
__global__ void detect_mask_kernel(const unsigned char* __restrict__ p) {
    __shared__ int f1, f23, f4;
    int tid = threadIdx.x;
    if (tid == 0) { f1 = 0; f23 = 0; f4 = 0; }
    __syncthreads();
    int l1 = 0, l23 = 0, l4 = 0;
    for (int i = tid; i < BB * SS; i += blockDim.x) {
        unsigned char v = p[i];
        if (v) {
            int r = i & 3;
            if (r == 1) l1 = 1;
            else if (r == 2 || r == 3) l23 = 1;
            if ((i & 7) == 4) l4 = 1;
        }
    }
    if (l1)  atomicOr(&f1, 1);
    if (l23) atomicOr(&f23, 1);
    if (l4)  atomicOr(&f4, 1);
    __syncthreads();
    if (tid == 0) {
        int flag;
        if (f1) flag = 0;
        else if (f23) flag = 2;
        else if (f4) flag = 1;
        else flag = 3;
        g_maskflag = flag;
    }
}

__global__ void repack_mask_kernel(const void* __restrict__ p) {
    int i = blockIdx.x * blockDim.x + threadIdx.x;
    if (i >= BB * SS) return;
    int flag = g_maskflag;
    bool mv;
    if (flag == 0)      mv = ((const unsigned char*)p)[i] != 0;
    else if (flag == 1) mv = ((const int*)p)[i] != 0;
    else if (flag == 2) mv = ((const float*)p)[i] != 0.0f;
    else                mv = ((const long long*)p)[i] != 0;
    g_mask[i] = mv ? -1.0e9f : 0.0f;
}

// ---------------------------------------------------------------------------
// tf32 helpers
// ---------------------------------------------------------------------------
__device__ __forceinline__ u32 tf32rn(float x) {
    u32 r; asm("cvt.rna.tf32.f32 %0, %1;" : "=r"(r) : "f"(x)); return r;
}
__device__ __forceinline__ void mma8(float* c, const u32* a, const u32* b) {
    asm volatile("mma.sync.aligned.m16n8k8.row.col.f32.tf32.tf32.f32 "
        "{%0,%1,%2,%3}, {%4,%5,%6,%7}, {%8,%9}, {%0,%1,%2,%3};"
        : "+f"(c[0]), "+f"(c[1]), "+f"(c[2]), "+f"(c[3])
        : "r"(a[0]), "r"(a[1]), "r"(a[2]), "r"(a[3]), "r"(b[0]), "r"(b[1]));
}

// ---------------------------------------------------------------------------
// Split-TF32 GEMM (NT) — unchanged from R4 (proven: 150us, tensor 56%)
// ---------------------------------------------------------------------------
#define BK 32
#define TSTR 36
#define TILE_F (128 * TSTR)
#define SM_AH 0
#define SM_BH TILE_F
#define SM_AL (2 * TILE_F)
#define SM_BL (3 * TILE_F)
#define GSM_BYTES (4 * TILE_F * 4)

__global__ __launch_bounds__(256, 1)
void gemm_mma(const float* __restrict__ Ain, const float* __restrict__ W,
              const float* __restrict__ bias, float* __restrict__ Cout,
              int srcsel, int dstsel)
{
    extern __shared__ float smf[];
    const float* A = srcsel ? g_attn : Ain;
    float* C = (dstsel == 0) ? Cout : (dstsel == 1 ? g_q : (dstsel == 2 ? g_k : g_v));

    int tid = threadIdx.x, wid = tid >> 5, lane = tid & 31;
    int gid = lane >> 2, tig = lane & 3;
    int m0 = (int)blockIdx.y << 7, n0 = (int)blockIdx.x << 7;
    int wm = (wid & 3) * 32, wn = (wid >> 2) * 64;

    const float* pA = A + (size_t)(m0 + (tid >> 3)) * DD + (tid & 7) * 4;
    const float* pB = W + (size_t)(n0 + (tid >> 3)) * DD + (tid & 7) * 4;
    int sbase = (tid >> 3) * TSTR + (tid & 7) * 4;

    float acc[2][8][4];
#pragma unroll
    for (int mt = 0; mt < 2; mt++)
#pragma unroll
        for (int nt = 0; nt < 8; nt++)
#pragma unroll
            for (int i = 0; i < 4; i++) acc[mt][nt][i] = 0.0f;

    float4 ra[4], rb[4];
#pragma unroll
    for (int j = 0; j < 4; j++) {
        ra[j] = *(const float4*)(pA + (size_t)j * 32 * DD);
        rb[j] = *(const float4*)(pB + (size_t)j * 32 * DD);
    }

    const int nk = DD / BK;
    for (int kt = 0; kt < nk; kt++) {
        __syncthreads();
#pragma unroll
        for (int j = 0; j < 4; j++) {
            int off = sbase + j * 32 * TSTR;
            u32 hx = tf32rn(ra[j].x), hy = tf32rn(ra[j].y);
            u32 hz = tf32rn(ra[j].z), hw = tf32rn(ra[j].w);
            float4 h = make_float4(__uint_as_float(hx), __uint_as_float(hy),
                                   __uint_as_float(hz), __uint_as_float(hw));
            *(float4*)&smf[SM_AH + off] = h;
            float4 l = make_float4(ra[j].x - h.x, ra[j].y - h.y,
                                   ra[j].z - h.z, ra[j].w - h.w);
            *(float4*)&smf[SM_AL + off] =
                make_float4(__uint_as_float(tf32rn(l.x)), __uint_as_float(tf32rn(l.y)),
                            __uint_as_float(tf32rn(l.z)), __uint_as_float(tf32rn(l.w)));
            hx = tf32rn(rb[j].x); hy = tf32rn(rb[j].y);
            hz = tf32rn(rb[j].z); hw = tf32rn(rb[j].w);
            h = make_float4(__uint_as_float(hx), __uint_as_float(hy),
                            __uint_as_float(hz), __uint_as_float(hw));
            *(float4*)&smf[SM_BH + off] = h;
            l = make_float4(rb[j].x - h.x, rb[j].y - h.y,
                            rb[j].z - h.z, rb[j].w - h.w);
            *(float4*)&smf[SM_BL + off] =
                make_float4(__uint_as_float(tf32rn(l.x)), __uint_as_float(tf32rn(l.y)),
                            __uint_as_float(tf32rn(l.z)), __uint_as_float(tf32rn(l.w)));
        }
        __syncthreads();
        if (kt + 1 < nk) {
#pragma unroll
            for (int j = 0; j < 4; j++) {
                ra[j] = *(const float4*)(pA + (size_t)j * 32 * DD + (kt + 1) * BK);
                rb[j] = *(const float4*)(pB + (size_t)j * 32 * DD + (kt + 1) * BK);
            }
        }
#pragma unroll
        for (int ks = 0; ks < 4; ks++) {
            int ko = ks * 8;
            u32 ah[2][4], al[2][4];
#pragma unroll
            for (int mt = 0; mt < 2; mt++) {
                int base = (wm + mt * 16 + gid) * TSTR + ko + tig;
                ah[mt][0] = __float_as_uint(smf[SM_AH + base]);
                ah[mt][1] = __float_as_uint(smf[SM_AH + base + 8 * TSTR]);
                ah[mt][2] = __float_as_uint(smf[SM_AH + base + 4]);
                ah[mt][3] = __float_as_uint(smf[SM_AH + base + 8 * TSTR + 4]);
                al[mt][0] = __float_as_uint(smf[SM_AL + base]);
                al[mt][1] = __float_as_uint(smf[SM_AL + base + 8 * TSTR]);
                al[mt][2] = __float_as_uint(smf[SM_AL + base + 4]);
                al[mt][3] = __float_as_uint(smf[SM_AL + base + 8 * TSTR + 4]);
            }
            u32 bh[8][2], bl[8][2];
#pragma unroll
            for (int nt = 0; nt < 8; nt++) {
                int base = (wn + nt * 8 + gid) * TSTR + ko + tig;
                bh[nt][0] = __float_as_uint(smf[SM_BH + base]);
                bh[nt][1] = __float_as_uint(smf[SM_BH + base + 4]);
                bl[nt][0] = __float_as_uint(smf[SM_BL + base]);
                bl[nt][1] = __float_as_uint(smf[SM_BL + base + 4]);
            }
#pragma unroll
            for (int mt = 0; mt < 2; mt++)
#pragma unroll
                for (int nt = 0; nt < 8; nt++) {
                    mma8(acc[mt][nt], ah[mt], bh[nt]);
                    mma8(acc[mt][nt], ah[mt], bl[nt]);
                    mma8(acc[mt][nt], al[mt], bh[nt]);
                }
        }
    }

#pragma unroll
    for (int mt = 0; mt < 2; mt++)
#pragma unroll
        for (int nt = 0; nt < 8; nt++) {
            int m = m0 + wm + mt * 16 + gid;
            int n = n0 + wn + nt * 8 + tig * 2;
            float b0 = bias[n], b1 = bias[n + 1];
            float2 p0 = make_float2(acc[mt][nt][0] + b0, acc[mt][nt][1] + b1);
            float2 p1 = make_float2(acc[mt][nt][2] + b0, acc[mt][nt][3] + b1);
            if (dstsel == 0) {
                *(float2*)&C[(size_t)m * DD + n] = p0;
                *(float2*)&C[(size_t)(m + 8) * DD + n] = p1;
            } else {
                int h = n >> 6, hd = n & 63;
                int b_ = m >> 11, s = m & 2047;
                *(float2*)&C[(((size_t)(b_ * 16 + h)) * SS + s) * HD + hd] = p0;
                int b2 = (m + 8) >> 11, s2 = (m + 8) & 2047;
                *(float2*)&C[(((size_t)(b2 * 16 + h)) * SS + s2) * HD + hd] = p1;
            }
        }
}

// ---------------------------------------------------------------------------
// Tensorized flash attention (split-tf32, mma.sync).
// CTA: 128 q-rows x one (b,h). 8 warps, warp w -> q rows [16w,16w+16).
// smem stride 68 floats (mod 32 = 4 -> conflict-free frag loads).
// QK^T: Q frags in regs (hi/lo), K pre-split in smem -> 3 MMAs.
// PV:  P via warp-private smem (split at load), V pre-split -> 3 MMAs.
// ---------------------------------------------------------------------------
#define SFL 68
#define FSM_FLOATS (4 * 4352 + 8704)
#define FSM_BYTES  (FSM_FLOATS * 4)   // 104448

__global__ __launch_bounds__(256, 1)
void flash_mma()
{
    extern __shared__ float sm[];
    float* sKh = sm;
    float* sKl = sm + 4352;
    float* sVh = sm + 8704;
    float* sVl = sm + 13056;
    float* sP  = sm + 17408;   // also Q staging (warp-private regions)

    int tid = threadIdx.x, wid = tid >> 5, lane = tid & 31;
    int gid = lane >> 2, tig = lane & 3;
    int bh = blockIdx.y, b = bh >> 4, h = bh & 15;
    int qt = (int)gridDim.x - 1 - (int)blockIdx.x;   // heavy blocks first
    int q0 = qt << 7;

    const float* Qp = g_q + ((size_t)bh * SS + q0) * HD;
    const float* Kbase = g_k + (size_t)bh * SS * HD;
    const float* Vbase = g_v + (size_t)bh * SS * HD;

    // Stage Q (warp-local rows) into sP, then extract hi/lo fragments to regs.
    {
        int r = tid >> 1, cb = (tid & 1) * 32;
#pragma unroll
        for (int c4 = 0; c4 < 8; c4++)
            *(float4*)&sP[r * SFL + cb + c4 * 4] =
                *(const float4*)(Qp + r * HD + cb + c4 * 4);
    }
    __syncwarp();

    int r0 = wid * 16 + gid;           // local row (and r0+8)
    int grow0 = q0 + r0;               // global rows grow0, grow0+8
    u32 qh[8][4], ql[8][4];
#pragma unroll
    for (int ks = 0; ks < 8; ks++) {
        int c = ks * 8 + tig;
        float f0 = sP[r0 * SFL + c];
        float f1 = sP[(r0 + 8) * SFL + c];
        float f2 = sP[r0 * SFL + c + 4];
        float f3 = sP[(r0 + 8) * SFL + c + 4];
        qh[ks][0] = tf32rn(f0); ql[ks][0] = tf32rn(f0 - __uint_as_float(qh[ks][0]));
        qh[ks][1] = tf32rn(f1); ql[ks][1] = tf32rn(f1 - __uint_as_float(qh[ks][1]));
        qh[ks][2] = tf32rn(f2); ql[ks][2] = tf32rn(f2 - __uint_as_float(qh[ks][2]));
        qh[ks][3] = tf32rn(f3); ql[ks][3] = tf32rn(f3 - __uint_as_float(qh[ks][3]));
    }
    __syncwarp();

    float mi0 = -1e30f, mi1 = -1e30f, li0 = 0.0f, li1 = 0.0f;
    float o[8][4];
#pragma unroll
    for (int nt = 0; nt < 8; nt++)
#pragma unroll
        for (int i = 0; i < 4; i++) o[nt][i] = 0.0f;

    int jmax = 2 * qt + 1;
    for (int jt = 0; jt <= jmax; jt++) {
        int j0 = jt << 6;
        __syncthreads();   // previous tile's K/V reads done before overwrite
        {
            int r = tid >> 2, cb = (tid & 3) * 16;
            const float* kp = Kbase + (size_t)(j0 + r) * HD + cb;
            const float* vp = Vbase + (size_t)(j0 + r) * HD + cb;
            int so = r * SFL + cb;
#pragma unroll
            for (int c4 = 0; c4 < 4; c4++) {
                float4 f = *(const float4*)(kp + c4 * 4);
                float4 hv, lv;
                hv.x = __uint_as_float(tf32rn(f.x)); lv.x = __uint_as_float(tf32rn(f.x - hv.x));
                hv.y = __uint_as_float(tf32rn(f.y)); lv.y = __uint_as_float(tf32rn(f.y - hv.y));
                hv.z = __uint_as_float(tf32rn(f.z)); lv.z = __uint_as_float(tf32rn(f.z - hv.z));
                hv.w = __uint_as_float(tf32rn(f.w)); lv.w = __uint_as_float(tf32rn(f.w - hv.w));
                *(float4*)&sKh[so + c4 * 4] = hv;
                *(float4*)&sKl[so + c4 * 4] = lv;
                f = *(const float4*)(vp + c4 * 4);
                hv.x = __uint_as_float(tf32rn(f.x)); lv.x = __uint_as_float(tf32rn(f.x - hv.x));
                hv.y = __uint_as_float(tf32rn(f.y)); lv.y = __uint_as_float(tf32rn(f.y - hv.y));
                hv.z = __uint_as_float(tf32rn(f.z)); lv.z = __uint_as_float(tf32rn(f.z - hv.z));
                hv.w = __uint_as_float(tf32rn(f.w)); lv.w = __uint_as_float(tf32rn(f.w - hv.w));
                *(float4*)&sVh[so + c4 * 4] = hv;
                *(float4*)&sVl[so + c4 * 4] = lv;
            }
        }
        __syncthreads();

        bool active = (j0 <= q0 + wid * 16 + 15);
        if (!active) continue;

        // S = Q K^T  (split-tf32, 3 MMAs)
        float s[8][4];
#pragma unroll
        for (int nt = 0; nt < 8; nt++)
#pragma unroll
            for (int i = 0; i < 4; i++) s[nt][i] = 0.0f;
#pragma unroll
        for (int ks = 0; ks < 8; ks++) {
            int kc = ks * 8 + tig;
#pragma unroll
            for (int nt = 0; nt < 8; nt++) {
                int kr = (nt * 8 + gid) * SFL + kc;
                u32 kb[2], kl2[2];
                kb[0]  = __float_as_uint(sKh[kr]);
                kb[1]  = __float_as_uint(sKh[kr + 4]);
                kl2[0] = __float_as_uint(sKl[kr]);
                kl2[1] = __float_as_uint(sKl[kr + 4]);
                mma8(s[nt], qh[ks], kb);
                mma8(s[nt], qh[ks], kl2);
                mma8(s[nt], ql[ks], kb);
            }
        }

        // scale + pad mask + causal
        bool applyC = (j0 + 63 > q0 + wid * 16);
        const float* mrow = g_mask + b * SS + j0;
#pragma unroll
        for (int nt = 0; nt < 8; nt++) {
            int cc = nt * 8 + 2 * tig;
            float2 md = *(const float2*)(mrow + cc);
            int gc0 = j0 + cc, gc1 = gc0 + 1;
            float v0 = s[nt][0] * 0.125f + md.x;
            float v1 = s[nt][1] * 0.125f + md.y;
            float v2 = s[nt][2] * 0.125f + md.x;
            float v3 = s[nt][3] * 0.125f + md.y;
            if (applyC) {
                if (gc0 > grow0)     v0 = -1.0e9f;
                if (gc1 > grow0)     v1 = -1.0e9f;
                if (gc0 > grow0 + 8) v2 = -1.0e9f;
                if (gc1 > grow0 + 8) v3 = -1.0e9f;
            }
            s[nt][0] = v0; s[nt][1] = v1; s[nt][2] = v2; s[nt][3] = v3;
        }

        // online softmax (rows r0 via c0/c1, r0+8 via c2/c3; 4 lanes per row)
        float rm0 = -1e30f, rm1 = -1e30f;
#pragma unroll
        for (int nt = 0; nt < 8; nt++) {
            rm0 = fmaxf(rm0, fmaxf(s[nt][0], s[nt][1]));
            rm1 = fmaxf(rm1, fmaxf(s[nt][2], s[nt][3]));
        }
        rm0 = fmaxf(rm0, __shfl_xor_sync(0xffffffffu, rm0, 1));
        rm0 = fmaxf(rm0, __shfl_xor_sync(0xffffffffu, rm0, 2));
        rm1 = fmaxf(rm1, __shfl_xor_sync(0xffffffffu, rm1, 1));
        rm1 = fmaxf(rm1, __shfl_xor_sync(0xffffffffu, rm1, 2));
        float mn0 = fmaxf(mi0, rm0), mn1 = fmaxf(mi1, rm1);
        float c0 = exp2f((mi0 - mn0) * LOG2E), c1 = exp2f((mi1 - mn1) * LOG2E);
        mi0 = mn0; mi1 = mn1;
        float rs0 = 0.0f, rs1 = 0.0f;
#pragma unroll
        for (int nt = 0; nt < 8; nt++) {
            s[nt][0] = exp2f((s[nt][0] - mn0) * LOG2E);
            s[nt][1] = exp2f((s[nt][1] - mn0) * LOG2E);
            s[nt][2] = exp2f((s[nt][2] - mn1) * LOG2E);
            s[nt][3] = exp2f((s[nt][3] - mn1) * LOG2E);
            rs0 += s[nt][0] + s[nt][1];
            rs1 += s[nt][2] + s[nt][3];
        }
        rs0 += __shfl_xor_sync(0xffffffffu, rs0, 1);
        rs0 += __shfl_xor_sync(0xffffffffu, rs0, 2);
        rs1 += __shfl_xor_sync(0xffffffffu, rs1, 1);
        rs1 += __shfl_xor_sync(0xffffffffu, rs1, 2);
        li0 = li0 * c0 + rs0;
        li1 = li1 * c1 + rs1;
#pragma unroll
        for (int nt = 0; nt < 8; nt++) {
            o[nt][0] *= c0; o[nt][1] *= c0;
            o[nt][2] *= c1; o[nt][3] *= c1;
        }

        // P -> warp-private smem
#pragma unroll
        for (int nt = 0; nt < 8; nt++) {
            int cc = nt * 8 + 2 * tig;
            *(float2*)&sP[r0 * SFL + cc]       = make_float2(s[nt][0], s[nt][1]);
            *(float2*)&sP[(r0 + 8) * SFL + cc] = make_float2(s[nt][2], s[nt][3]);
        }
        __syncwarp();

        // O += P V  (split-tf32, 3 MMAs)
#pragma unroll
        for (int ks = 0; ks < 8; ks++) {
            int c = ks * 8 + tig;
            float f0 = sP[r0 * SFL + c];
            float f1 = sP[(r0 + 8) * SFL + c];
            float f2 = sP[r0 * SFL + c + 4];
            float f3 = sP[(r0 + 8) * SFL + c + 4];
            u32 ph[4], pl[4];
            ph[0] = tf32rn(f0); pl[0] = tf32rn(f0 - __uint_as_float(ph[0]));
            ph[1] = tf32rn(f1); pl[1] = tf32rn(f1 - __uint_as_float(ph[1]));
            ph[2] = tf32rn(f2); pl[2] = tf32rn(f2 - __uint_as_float(ph[2]));
            ph[3] = tf32rn(f3); pl[3] = tf32rn(f3 - __uint_as_float(ph[3]));
            int vr0 = (ks * 8 + tig) * SFL, vr1 = (ks * 8 + tig + 4) * SFL;
#pragma unroll
            for (int nt = 0; nt < 8; nt++) {
                int vc = nt * 8 + gid;
                u32 vb[2], vl2[2];
                vb[0]  = __float_as_uint(sVh[vr0 + vc]);
                vb[1]  = __float_as_uint(sVh[vr1 + vc]);
                vl2[0] = __float_as_uint(sVl[vr0 + vc]);
                vl2[1] = __float_as_uint(sVl[vr1 + vc]);
                mma8(o[nt], ph, vb);
                mma8(o[nt], pl, vb);
                mma8(o[nt], ph, vl2);
            }
        }
        __syncwarp();
    }

    // epilogue: g_attn[b, row, h*64+col] = o / l
    float i0 = 1.0f / li0, i1 = 1.0f / li1;
#pragma unroll
    for (int nt = 0; nt < 8; nt++) {
        int col = (h << 6) + nt * 8 + 2 * tig;
        *(float2*)&g_attn[(((size_t)(b * SS + grow0)) << 10) + col] =
            make_float2(o[nt][0] * i0, o[nt][1] * i0);
        *(float2*)&g_attn[(((size_t)(b * SS + grow0 + 8)) << 10) + col] =
            make_float2(o[nt][2] * i1, o[nt][3] * i1);
    }
}

// ---------------------------------------------------------------------------
extern "C" void kernel_launch(void* const* d_in, const int* in_sizes, int n_in,
                              void* d_out, int out_size) {
    const float* x  = (const float*)d_in[0];
    const void*  pm = d_in[1];
    const float* Wq = (const float*)d_in[2];
    const float* bq = (const float*)d_in[3];
    const float* Wk = (const float*)d_in[4];
    const float* bk = (const float*)d_in[5];
    const float* Wv = (const float*)d_in[6];
    const float* bv = (const float*)d_in[7];
    const float* Wo = (const float*)d_in[8];
    const float* bo = (const float*)d_in[9];
    float* out = (float*)d_out;

    cudaFuncSetAttribute(gemm_mma, cudaFuncAttributeMaxDynamicSharedMemorySize, GSM_BYTES);
    cudaFuncSetAttribute(flash_mma, cudaFuncAttributeMaxDynamicSharedMemorySize, FSM_BYTES);

    detect_mask_kernel<<<1, 256>>>((const unsigned char*)pm);
    repack_mask_kernel<<<16, 256>>>(pm);

    dim3 gg(DD / 128, MM / 128);   // (8, 32)
    gemm_mma<<<gg, 256, GSM_BYTES>>>(x, Wq, bq, nullptr, 0, 1);
    gemm_mma<<<gg, 256, GSM_BYTES>>>(x, Wk, bk, nullptr, 0, 2);
    gemm_mma<<<gg, 256, GSM_BYTES>>>(x, Wv, bv, nullptr, 0, 3);

    flash_mma<<<dim3(SS / 128, BB * HH), 256, FSM_BYTES>>>();

    gemm_mma<<<gg, 256, GSM_BYTES>>>(nullptr, Wo, bo, out, 1, 0);
}

// round 11
// speedup vs baseline: 2.3222x; 1.7337x over previous
#include <cuda_runtime.h>
#include <cuda_bf16.h>
#include <cstdint>

typedef unsigned int u32;

#define BB 2
#define SS 2048
#define DD 1024
#define HH 16
#define HD 64
#define MM 4096
#define LOG2E 1.4426950408889634f

__device__ float g_q[MM * DD];
__device__ float g_k[MM * DD];
__device__ float g_v[MM * DD];
__device__ float g_attn[MM * DD];
__device__ float g_mask[BB * SS];
__device__ int   g_maskflag;

// ---------------------------------------------------------------------------
// Mask detect / repack (proven)
// ---------------------------------------------------------------------------
__global__ void detect_mask_kernel(const unsigned char* __restrict__ p) {
    __shared__ int f1, f23, f4;
    int tid = threadIdx.x;
    if (tid == 0) { f1 = 0; f23 = 0; f4 = 0; }
    __syncthreads();
    int l1 = 0, l23 = 0, l4 = 0;
    for (int i = tid; i < BB * SS; i += blockDim.x) {
        unsigned char v = p[i];
        if (v) {
            int r = i & 3;
            if (r == 1) l1 = 1;
            else if (r == 2 || r == 3) l23 = 1;
            if ((i & 7) == 4) l4 = 1;
        }
    }
    if (l1)  atomicOr(&f1, 1);
    if (l23) atomicOr(&f23, 1);
    if (l4)  atomicOr(&f4, 1);
    __syncthreads();
    if (tid == 0) {
        int flag;
        if (f1) flag = 0;
        else if (f23) flag = 2;
        else if (f4) flag = 1;
        else flag = 3;
        g_maskflag = flag;
    }
}

__global__ void repack_mask_kernel(const void* __restrict__ p) {
    int i = blockIdx.x * blockDim.x + threadIdx.x;
    if (i >= BB * SS) return;
    int flag = g_maskflag;
    bool mv;
    if (flag == 0)      mv = ((const unsigned char*)p)[i] != 0;
    else if (flag == 1) mv = ((const int*)p)[i] != 0;
    else if (flag == 2) mv = ((const float*)p)[i] != 0.0f;
    else                mv = ((const long long*)p)[i] != 0;
    g_mask[i] = mv ? -1.0e9f : 0.0f;
}

// ---------------------------------------------------------------------------
// bf16 helpers
// ---------------------------------------------------------------------------
// Split (a,b) into hi bf16x2 pack + lo residual bf16x2 pack. a -> low half.
__device__ __forceinline__ void bsplit(float a, float b, u32& h, u32& l) {
    __nv_bfloat162 hh = __floats2bfloat162_rn(a, b);
    float ra_ = a - __bfloat162float(hh.x);
    float rb_ = b - __bfloat162float(hh.y);
    __nv_bfloat162 ll = __floats2bfloat162_rn(ra_, rb_);
    h = *(u32*)&hh; l = *(u32*)&ll;
}
__device__ __forceinline__ void mma16(float* c, const u32* a, const u32* b) {
    asm volatile("mma.sync.aligned.m16n8k16.row.col.f32.bf16.bf16.f32 "
        "{%0,%1,%2,%3}, {%4,%5,%6,%7}, {%8,%9}, {%0,%1,%2,%3};"
        : "+f"(c[0]), "+f"(c[1]), "+f"(c[2]), "+f"(c[3])
        : "r"(a[0]), "r"(a[1]), "r"(a[2]), "r"(a[3]), "r"(b[0]), "r"(b[1]));
}
__device__ __forceinline__ void sts2(u32* base, u32 a, u32 b) {
    asm volatile("st.shared.v2.b32 [%0], {%1,%2};"
        :: "l"(__cvta_generic_to_shared(base)), "r"(a), "r"(b) : "memory");
}
__device__ __forceinline__ void sts4(u32* base, u32 a, u32 b, u32 c, u32 d) {
    asm volatile("st.shared.v4.b32 [%0], {%1,%2,%3,%4};"
        :: "l"(__cvta_generic_to_shared(base)), "r"(a), "r"(b), "r"(c), "r"(d) : "memory");
}

// ---------------------------------------------------------------------------
// Split-BF16 GEMM (NT): C[m,n] = sum_k A[m,k]*W[n,k] + bias[n]
// y = hi*hi + hi*lo + lo*hi (dropped lo*lo ~2^-18).
// CTA 128x128, BK=32 (2 k16-steps), 256 thr. smem u32 tiles stride 20
// (20*gid+tig mod 32 -> conflict-free fragment LDS).
// ---------------------------------------------------------------------------
#define SRU 20
#define TU (128 * SRU)

__global__ __launch_bounds__(256, 1)
void gemm_mma(const float* __restrict__ Ain, const float* __restrict__ W,
              const float* __restrict__ bias, float* __restrict__ Cout,
              int srcsel, int dstsel)
{
    __shared__ u32 smAh[TU], smAl[TU], smBh[TU], smBl[TU];

    const float* A = srcsel ? g_attn : Ain;
    float* C = (dstsel == 0) ? Cout : (dstsel == 1 ? g_q : (dstsel == 2 ? g_k : g_v));

    int tid = threadIdx.x, wid = tid >> 5, lane = tid & 31;
    int gid = lane >> 2, tig = lane & 3;
    int m0 = (int)blockIdx.y << 7, n0 = (int)blockIdx.x << 7;
    int wm = (wid & 3) * 32, wn = (wid >> 2) * 64;

    const float* pA = A + (size_t)(m0 + (tid >> 3)) * DD + (tid & 7) * 4;
    const float* pB = W + (size_t)(n0 + (tid >> 3)) * DD + (tid & 7) * 4;
    int sbase = (tid >> 3) * SRU + (tid & 7) * 2;

    float acc[2][8][4];
#pragma unroll
    for (int mt = 0; mt < 2; mt++)
#pragma unroll
        for (int nt = 0; nt < 8; nt++)
#pragma unroll
            for (int i = 0; i < 4; i++) acc[mt][nt][i] = 0.0f;

    float4 ra[4], rb[4];
#pragma unroll
    for (int j = 0; j < 4; j++) {
        ra[j] = *(const float4*)(pA + (size_t)j * 32 * DD);
        rb[j] = *(const float4*)(pB + (size_t)j * 32 * DD);
    }

    const int nk = DD / 32;
    for (int kt = 0; kt < nk; kt++) {
        __syncthreads();
#pragma unroll
        for (int j = 0; j < 4; j++) {
            int off = sbase + j * 32 * SRU;
            u32 h0, l0, h1, l1;
            bsplit(ra[j].x, ra[j].y, h0, l0);
            bsplit(ra[j].z, ra[j].w, h1, l1);
            sts2(smAh + off, h0, h1);
            sts2(smAl + off, l0, l1);
            bsplit(rb[j].x, rb[j].y, h0, l0);
            bsplit(rb[j].z, rb[j].w, h1, l1);
            sts2(smBh + off, h0, h1);
            sts2(smBl + off, l0, l1);
        }
        __syncthreads();
        if (kt + 1 < nk) {
#pragma unroll
            for (int j = 0; j < 4; j++) {
                ra[j] = *(const float4*)(pA + (size_t)j * 32 * DD + (kt + 1) * 32);
                rb[j] = *(const float4*)(pB + (size_t)j * 32 * DD + (kt + 1) * 32);
            }
        }
#pragma unroll
        for (int ks = 0; ks < 2; ks++) {
            int ko = ks * 8;
            u32 ah[2][4], al[2][4];
#pragma unroll
            for (int mt = 0; mt < 2; mt++) {
                int base = (wm + mt * 16 + gid) * SRU + ko + tig;
                ah[mt][0] = smAh[base];
                ah[mt][1] = smAh[base + 8 * SRU];
                ah[mt][2] = smAh[base + 4];
                ah[mt][3] = smAh[base + 8 * SRU + 4];
                al[mt][0] = smAl[base];
                al[mt][1] = smAl[base + 8 * SRU];
                al[mt][2] = smAl[base + 4];
                al[mt][3] = smAl[base + 8 * SRU + 4];
            }
            u32 bh[8][2], bl[8][2];
#pragma unroll
            for (int nt = 0; nt < 8; nt++) {
                int base = (wn + nt * 8 + gid) * SRU + ko + tig;
                bh[nt][0] = smBh[base];
                bh[nt][1] = smBh[base + 4];
                bl[nt][0] = smBl[base];
                bl[nt][1] = smBl[base + 4];
            }
#pragma unroll
            for (int mt = 0; mt < 2; mt++)
#pragma unroll
                for (int nt = 0; nt < 8; nt++) {
                    mma16(acc[mt][nt], ah[mt], bh[nt]);
                    mma16(acc[mt][nt], ah[mt], bl[nt]);
                    mma16(acc[mt][nt], al[mt], bh[nt]);
                }
        }
    }

#pragma unroll
    for (int mt = 0; mt < 2; mt++)
#pragma unroll
        for (int nt = 0; nt < 8; nt++) {
            int m = m0 + wm + mt * 16 + gid;
            int n = n0 + wn + nt * 8 + tig * 2;
            float b0 = bias[n], b1 = bias[n + 1];
            float2 p0 = make_float2(acc[mt][nt][0] + b0, acc[mt][nt][1] + b1);
            float2 p1 = make_float2(acc[mt][nt][2] + b0, acc[mt][nt][3] + b1);
            if (dstsel == 0) {
                *(float2*)&C[(size_t)m * DD + n] = p0;
                *(float2*)&C[(size_t)(m + 8) * DD + n] = p1;
            } else {
                int h = n >> 6, hd = n & 63;
                int b_ = m >> 11, s = m & 2047;
                *(float2*)&C[(((size_t)(b_ * 16 + h)) * SS + s) * HD + hd] = p0;
                int b2 = (m + 8) >> 11, s2 = (m + 8) & 2047;
                *(float2*)&C[(((size_t)(b2 * 16 + h)) * SS + s2) * HD + hd] = p1;
            }
        }
}

// ---------------------------------------------------------------------------
// Split-BF16 flash attention (m16n8k16).
// CTA: 128 q-rows x one (b,h). 8 warps, warp w -> rows [16w,16w+16).
// Q frags direct from gmem (regs, hi/lo). K smem [64][36] u32 pairs (along d).
// V smem TRANSPOSED [32 jpair][72] u32 (pairs along j) -> native B frags.
// P comes straight from QK^T C-fragments (layout identity) — no smem trip.
// ---------------------------------------------------------------------------
#define KSTR 36
#define VSTR 72

__global__ __launch_bounds__(256, 1)
void flash_mma()
{
    __shared__ u32 sKh[64 * KSTR], sKl[64 * KSTR];
    __shared__ u32 sVh[32 * VSTR], sVl[32 * VSTR];

    int tid = threadIdx.x, wid = tid >> 5, lane = tid & 31;
    int gid = lane >> 2, tig = lane & 3;
    int bh = blockIdx.y, b = bh >> 4, h = bh & 15;
    int qt = (int)gridDim.x - 1 - (int)blockIdx.x;   // heavy blocks first
    int q0 = qt << 7;

    const float* Kbase = g_k + (size_t)bh * SS * HD;
    const float* Vbase = g_v + (size_t)bh * SS * HD;

    int r0 = wid * 16 + gid;
    int grow0 = q0 + r0;

    // Q fragments direct from gmem
    u32 qh[4][4], ql[4][4];
    {
        const float* q0p = g_q + ((size_t)bh * SS + grow0) * HD;
        const float* q1p = q0p + 8 * HD;
#pragma unroll
        for (int ks = 0; ks < 4; ks++) {
            int c = 16 * ks + 2 * tig;
            float2 f0 = *(const float2*)(q0p + c);
            float2 f1 = *(const float2*)(q1p + c);
            float2 f2 = *(const float2*)(q0p + c + 8);
            float2 f3 = *(const float2*)(q1p + c + 8);
            bsplit(f0.x, f0.y, qh[ks][0], ql[ks][0]);
            bsplit(f1.x, f1.y, qh[ks][1], ql[ks][1]);
            bsplit(f2.x, f2.y, qh[ks][2], ql[ks][2]);
            bsplit(f3.x, f3.y, qh[ks][3], ql[ks][3]);
        }
    }

    float mi0 = -1e30f, mi1 = -1e30f, li0 = 0.0f, li1 = 0.0f;
    float o[8][4];
#pragma unroll
    for (int nt = 0; nt < 8; nt++)
#pragma unroll
        for (int i = 0; i < 4; i++) o[nt][i] = 0.0f;

    int jmax = 2 * qt + 1;
    for (int jt = 0; jt <= jmax; jt++) {
        int j0 = jt << 6;
        __syncthreads();   // prev tile K/V reads done
        {
            // K: row r, 16 cols starting cb -> 8 u32 pairs along d
            int r = tid >> 2, cb = (tid & 3) * 16;
            const float* kp = Kbase + (size_t)(j0 + r) * HD + cb;
            int so = r * KSTR + (cb >> 1);
#pragma unroll
            for (int c4 = 0; c4 < 4; c4++) {
                float4 f = *(const float4*)(kp + c4 * 4);
                u32 h0, l0, h1, l1;
                bsplit(f.x, f.y, h0, l0);
                bsplit(f.z, f.w, h1, l1);
                sts2(sKh + so + c4 * 2, h0, h1);
                sts2(sKl + so + c4 * 2, l0, l1);
            }
            // V transposed: jpair jp, 8 n-cols; pack across rows 2jp/2jp+1
            int jp = tid >> 3, hd0 = (tid & 7) * 8;
            const float* vp0 = Vbase + (size_t)(j0 + 2 * jp) * HD + hd0;
            const float* vp1 = vp0 + HD;
            float4 a0 = *(const float4*)(vp0);
            float4 a1 = *(const float4*)(vp0 + 4);
            float4 c0_ = *(const float4*)(vp1);
            float4 c1_ = *(const float4*)(vp1 + 4);
            u32 vh[8], vl[8];
            bsplit(a0.x, c0_.x, vh[0], vl[0]);
            bsplit(a0.y, c0_.y, vh[1], vl[1]);
            bsplit(a0.z, c0_.z, vh[2], vl[2]);
            bsplit(a0.w, c0_.w, vh[3], vl[3]);
            bsplit(a1.x, c1_.x, vh[4], vl[4]);
            bsplit(a1.y, c1_.y, vh[5], vl[5]);
            bsplit(a1.z, c1_.z, vh[6], vl[6]);
            bsplit(a1.w, c1_.w, vh[7], vl[7]);
            int vo = jp * VSTR + hd0;
            sts4(sVh + vo, vh[0], vh[1], vh[2], vh[3]);
            sts4(sVh + vo + 4, vh[4], vh[5], vh[6], vh[7]);
            sts4(sVl + vo, vl[0], vl[1], vl[2], vl[3]);
            sts4(sVl + vo + 4, vl[4], vl[5], vl[6], vl[7]);
        }
        __syncthreads();

        bool active = (j0 <= q0 + wid * 16 + 15);
        if (!active) continue;

        // S = Q K^T  (split-bf16, 3 MMAs)
        float s[8][4];
#pragma unroll
        for (int nt = 0; nt < 8; nt++)
#pragma unroll
            for (int i = 0; i < 4; i++) s[nt][i] = 0.0f;
#pragma unroll
        for (int ks = 0; ks < 4; ks++) {
#pragma unroll
            for (int nt = 0; nt < 8; nt++) {
                int kr = (nt * 8 + gid) * KSTR + 8 * ks + tig;
                u32 kb[2], kl2[2];
                kb[0]  = sKh[kr];
                kb[1]  = sKh[kr + 4];
                kl2[0] = sKl[kr];
                kl2[1] = sKl[kr + 4];
                mma16(s[nt], qh[ks], kb);
                mma16(s[nt], qh[ks], kl2);
                mma16(s[nt], ql[ks], kb);
            }
        }

        // scale + pad mask + causal
        bool applyC = (j0 + 63 > q0 + wid * 16);
        const float* mrow = g_mask + b * SS + j0;
#pragma unroll
        for (int nt = 0; nt < 8; nt++) {
            int cc = nt * 8 + 2 * tig;
            float2 md = *(const float2*)(mrow + cc);
            int gc0 = j0 + cc, gc1 = gc0 + 1;
            float v0 = s[nt][0] * 0.125f + md.x;
            float v1 = s[nt][1] * 0.125f + md.y;
            float v2 = s[nt][2] * 0.125f + md.x;
            float v3 = s[nt][3] * 0.125f + md.y;
            if (applyC) {
                if (gc0 > grow0)     v0 = -1.0e9f;
                if (gc1 > grow0)     v1 = -1.0e9f;
                if (gc0 > grow0 + 8) v2 = -1.0e9f;
                if (gc1 > grow0 + 8) v3 = -1.0e9f;
            }
            s[nt][0] = v0; s[nt][1] = v1; s[nt][2] = v2; s[nt][3] = v3;
        }

        // online softmax
        float rm0 = -1e30f, rm1 = -1e30f;
#pragma unroll
        for (int nt = 0; nt < 8; nt++) {
            rm0 = fmaxf(rm0, fmaxf(s[nt][0], s[nt][1]));
            rm1 = fmaxf(rm1, fmaxf(s[nt][2], s[nt][3]));
        }
        rm0 = fmaxf(rm0, __shfl_xor_sync(0xffffffffu, rm0, 1));
        rm0 = fmaxf(rm0, __shfl_xor_sync(0xffffffffu, rm0, 2));
        rm1 = fmaxf(rm1, __shfl_xor_sync(0xffffffffu, rm1, 1));
        rm1 = fmaxf(rm1, __shfl_xor_sync(0xffffffffu, rm1, 2));
        float mn0 = fmaxf(mi0, rm0), mn1 = fmaxf(mi1, rm1);
        float c0 = exp2f((mi0 - mn0) * LOG2E), c1 = exp2f((mi1 - mn1) * LOG2E);
        mi0 = mn0; mi1 = mn1;
        float rs0 = 0.0f, rs1 = 0.0f;
#pragma unroll
        for (int nt = 0; nt < 8; nt++) {
            s[nt][0] = exp2f((s[nt][0] - mn0) * LOG2E);
            s[nt][1] = exp2f((s[nt][1] - mn0) * LOG2E);
            s[nt][2] = exp2f((s[nt][2] - mn1) * LOG2E);
            s[nt][3] = exp2f((s[nt][3] - mn1) * LOG2E);
            rs0 += s[nt][0] + s[nt][1];
            rs1 += s[nt][2] + s[nt][3];
        }
        rs0 += __shfl_xor_sync(0xffffffffu, rs0, 1);
        rs0 += __shfl_xor_sync(0xffffffffu, rs0, 2);
        rs1 += __shfl_xor_sync(0xffffffffu, rs1, 1);
        rs1 += __shfl_xor_sync(0xffffffffu, rs1, 2);
        li0 = li0 * c0 + rs0;
        li1 = li1 * c1 + rs1;
#pragma unroll
        for (int nt = 0; nt < 8; nt++) {
            o[nt][0] *= c0; o[nt][1] *= c0;
            o[nt][2] *= c1; o[nt][3] *= c1;
        }

        // O += P V. P A-fragments come directly from the QK C-fragments:
        // k-step ks: a0=P[r0][16ks+2tig,+1]=s[2ks][0..1], a1=row r0+8,
        // a2=s[2ks+1][0..1], a3=s[2ks+1][2..3].
#pragma unroll
        for (int ks = 0; ks < 4; ks++) {
            u32 ph[4], pl[4];
            bsplit(s[2 * ks][0],     s[2 * ks][1],     ph[0], pl[0]);
            bsplit(s[2 * ks][2],     s[2 * ks][3],     ph[1], pl[1]);
            bsplit(s[2 * ks + 1][0], s[2 * ks + 1][1], ph[2], pl[2]);
            bsplit(s[2 * ks + 1][2], s[2 * ks + 1][3], ph[3], pl[3]);
#pragma unroll
            for (int nt = 0; nt < 8; nt++) {
                int vr = (8 * ks + tig) * VSTR + nt * 8 + gid;
                u32 vb[2], vl2[2];
                vb[0]  = sVh[vr];
                vb[1]  = sVh[vr + 4 * VSTR];
                vl2[0] = sVl[vr];
                vl2[1] = sVl[vr + 4 * VSTR];
                mma16(o[nt], ph, vb);
                mma16(o[nt], pl, vb);
                mma16(o[nt], ph, vl2);
            }
        }
    }

    // epilogue
    float i0 = 1.0f / li0, i1 = 1.0f / li1;
#pragma unroll
    for (int nt = 0; nt < 8; nt++) {
        int col = (h << 6) + nt * 8 + 2 * tig;
        *(float2*)&g_attn[(((size_t)(b * SS + grow0)) << 10) + col] =
            make_float2(o[nt][0] * i0, o[nt][1] * i0);
        *(float2*)&g_attn[(((size_t)(b * SS + grow0 + 8)) << 10) + col] =
            make_float2(o[nt][2] * i1, o[nt][3] * i1);
    }
}

// ---------------------------------------------------------------------------
extern "C" void kernel_launch(void* const* d_in, const int* in_sizes, int n_in,
                              void* d_out, int out_size) {
    const float* x  = (const float*)d_in[0];
    const void*  pm = d_in[1];
    const float* Wq = (const float*)d_in[2];
    const float* bq = (const float*)d_in[3];
    const float* Wk = (const float*)d_in[4];
    const float* bk = (const float*)d_in[5];
    const float* Wv = (const float*)d_in[6];
    const float* bv = (const float*)d_in[7];
    const float* Wo = (const float*)d_in[8];
    const float* bo = (const float*)d_in[9];
    float* out = (float*)d_out;

    detect_mask_kernel<<<1, 256>>>((const unsigned char*)pm);
    repack_mask_kernel<<<16, 256>>>(pm);

    dim3 gg(DD / 128, MM / 128);   // (8, 32)
    gemm_mma<<<gg, 256>>>(x, Wq, bq, nullptr, 0, 1);
    gemm_mma<<<gg, 256>>>(x, Wk, bk, nullptr, 0, 2);
    gemm_mma<<<gg, 256>>>(x, Wv, bv, nullptr, 0, 3);

    flash_mma<<<dim3(SS / 128, BB * HH), 256>>>();

    gemm_mma<<<gg, 256>>>(nullptr, Wo, bo, out, 1, 0);
}